// round 17
// baseline (speedup 1.0000x reference)
#include <cuda_runtime.h>
#include <cuda_bf16.h>
#include <cuda_fp16.h>
#include <cstdint>
#include <cstddef>
#include <cstring>

// ============================================================
// AdditiveAttention via single fp16 mma.sync GEMM:
//   scores[b,l] = sum_h tanh(qp[b,h] + kp[b,l,h]) * w_v[h]
// 3-stage continuous pipeline, one barrier per chunk.
// NEW (R17): keys fp32->fp16 conversion FUSED into the main kernel
// (LDG.128 one chunk ahead -> cvt -> STS). Removes the 768MB
// convert_keys pre-pass. B (W^T fp16) still via cp.async.
// Race-free: stage written at iter c was last read at iter c-2,
// fenced by the barriers at iters c-1 and c.
// ============================================================

constexpr int BB = 16, LKK = 8192, DD = 1024, HH = 1024;
constexpr int MTOT = BB * LKK;     // 131072 rows
constexpr int MT = 128;            // rows per CTA
constexpr int NT = 128;            // cols per n-pass
constexpr int KC = 64;             // k per chunk
constexpr int NC = DD / KC;        // 16 chunks per pass
constexpr int NPASS = HH / NT;     // 8 passes
constexpr int TOTC = NPASS * NC;   // 128 chunks, flat
constexpr int THREADS = 256;       // 8 warps: 4 (m) x 2 (n)
constexpr int ROWB = 144;          // smem pitch: 64 fp16 = 128B + 16B pad

// smem layout (bytes)
constexpr int ATILE  = MT * ROWB;            // 18432
constexpr int BTILE  = NT * ROWB;            // 18432
constexpr int STAGE  = ATILE + BTILE;        // 36864
constexpr int Q_OFF  = 3 * STAGE;            // 110592 (2 x 128 floats)
constexpr int WV_OFF = Q_OFF + 1024;         // 111616 (2 x 128 floats)
constexpr int RED_OFF= WV_OFF + 1024;        // 112640 (256 floats)
constexpr int SMEM_TOTAL = RED_OFF + 1024;   // 113664
static_assert(2 * SMEM_TOTAL <= 232448 - 2048, "2 CTA/SM smem");

// -------- device scratch (no runtime allocs allowed) --------
__device__ __align__(16) __half g_Wth[(size_t)HH * DD];       // W_k^T fp16 [h][d]
__device__ float g_q[BB * HH];

// ================= asm helpers =================
__device__ __forceinline__ uint32_t smem_u32(const void* p) {
    uint32_t a;
    asm("{ .reg .u64 t; cvta.to.shared.u64 t, %1; cvt.u32.u64 %0, t; }"
        : "=r"(a) : "l"(p));
    return a;
}

#define CPASYNC16(dst, src) \
    asm volatile("cp.async.cg.shared.global [%0], [%1], 16;" \
                 :: "r"(dst), "l"(src) : "memory")
#define CPASYNC_COMMIT() asm volatile("cp.async.commit_group;" ::: "memory")
#define CPASYNC_WAIT1()  asm volatile("cp.async.wait_group 1;" ::: "memory")
#define CPASYNC_WAIT0()  asm volatile("cp.async.wait_group 0;" ::: "memory")

#define LDSM4(r, addr) \
    asm volatile("ldmatrix.sync.aligned.m8n8.x4.shared.b16 {%0,%1,%2,%3}, [%4];" \
                 : "=r"((r)[0]), "=r"((r)[1]), "=r"((r)[2]), "=r"((r)[3]) \
                 : "r"(addr))

#define MMA16816(c, a, b0, b1) \
    asm volatile("mma.sync.aligned.m16n8k16.row.col.f32.f16.f16.f32 " \
                 "{%0,%1,%2,%3}, {%4,%5,%6,%7}, {%8,%9}, {%0,%1,%2,%3};" \
                 : "+f"((c)[0]), "+f"((c)[1]), "+f"((c)[2]), "+f"((c)[3]) \
                 : "r"((a)[0]), "r"((a)[1]), "r"((a)[2]), "r"((a)[3]), \
                   "r"(b0), "r"(b1))

#define STS64(addr, u0, u1) \
    asm volatile("st.shared.v2.b32 [%0], {%1,%2};" \
                 :: "r"(addr), "r"(u0), "r"(u1) : "memory")

// ================= prep kernels =================

// W_k [d][h] fp32 -> transposed fp16  g_Wth[h][d]
__global__ void wsplit_kernel(const float* __restrict__ Wk) {
    __shared__ float tile[32][33];
    const int h0 = blockIdx.x * 32;
    const int d0 = blockIdx.y * 32;
    const int tx = threadIdx.x;
    for (int j = threadIdx.y; j < 32; j += 8)
        tile[j][tx] = Wk[(size_t)(d0 + j) * HH + (h0 + tx)];
    __syncthreads();
    const int dx = d0 + tx;
    for (int j = threadIdx.y; j < 32; j += 8)
        g_Wth[(size_t)(h0 + j) * DD + dx] = __float2half_rn(tile[tx][j]);
}

// g_q[b][h] = sum_d queries[b,d] * W_q[d,h]; grid (H/256, BB)
__global__ void qproj_kernel(const float* __restrict__ queries,
                             const float* __restrict__ Wq) {
    __shared__ float qrow[DD];
    const int b = blockIdx.y;
    const int h = blockIdx.x * 256 + threadIdx.x;
    for (int i = threadIdx.x; i < DD; i += 256)
        qrow[i] = queries[(size_t)b * DD + i];
    __syncthreads();
    float acc = 0.f;
    #pragma unroll 8
    for (int d = 0; d < DD; ++d)
        acc += qrow[d] * Wq[(size_t)d * HH + h];
    g_q[b * HH + h] = acc;
}

// ================= main fused kernel =================
__global__ void __launch_bounds__(THREADS, 2)
additive_attn_main(const float* __restrict__ keys,
                   const float* __restrict__ wv, float* __restrict__ out) {
    extern __shared__ char smem[];
    const uint32_t sb = smem_u32(smem);
    const int tid  = threadIdx.x;
    const int lane = tid & 31;
    const int wid  = tid >> 5;
    const int wm   = wid >> 1;   // 0..3 -> 32 rows each
    const int wn   = wid & 1;    // 0..1 -> 64 cols each
    const int m0   = blockIdx.x * MT;
    const int b    = m0 >> 13;   // 8192 rows per batch

    float* q_s  = reinterpret_cast<float*>(smem + Q_OFF);   // [2][128]
    float* wv_s = reinterpret_cast<float*>(smem + WV_OFF);  // [2][128]
    float* red  = reinterpret_cast<float*>(smem + RED_OFF);

    // per-lane ldmatrix offsets (verified R13/R15/R16)
    const uint32_t a_lane = (uint32_t)((lane % 16) * ROWB + (lane / 16) * 16);
    const uint32_t b_lane = (uint32_t)(((lane & 7) + ((lane >> 4) << 3)) * ROWB
                                       + ((lane & 8) ? 16 : 0));

    // ---- B (W^T fp16) cp.async coordinates ----
    const int crow = tid >> 3;   // 0..31
    const int cseg = tid & 7;    // 0..7
    const __half* bsrc0 = g_Wth + (size_t)crow * DD + cseg * 8;
    const uint32_t bdst0 = (uint32_t)(crow * ROWB + cseg * 16);

    auto issue_b = [&](int c) {
        const int k0 = (c & (NC - 1)) * KC;
        const size_t boff = (size_t)((c >> 4) * NT) * DD + k0;
        const uint32_t stg = sb + (c % 3) * STAGE + ATILE;
        #pragma unroll
        for (int t = 0; t < 4; ++t)
            CPASYNC16(stg + bdst0 + t * 32 * ROWB,
                      bsrc0 + (size_t)t * 32 * DD + boff);
        CPASYNC_COMMIT();
    };

    // ---- A (keys fp32 -> fp16) fused conversion coordinates ----
    // half hf covers rows [64*hf, 64*hf+64); per thread 4 float4:
    //   row = (tid>>4) + 16*p + 64*hf, colseg = tid&15
    const int arow = tid >> 4;    // 0..15
    const int acol = tid & 15;    // float4 index within 64-float chunk row
    const float* asrc0 = keys + (size_t)(m0 + arow) * DD + acol * 4;

    auto ldg_a = [&](int c, int hf, float4* v) {
        const float* src = asrc0 + (size_t)(64 * hf) * DD + (c & (NC - 1)) * KC;
        #pragma unroll
        for (int p = 0; p < 4; ++p)
            v[p] = *reinterpret_cast<const float4*>(src + (size_t)(16 * p) * DD);
    };
    auto sts_a = [&](int c, int hf, const float4* v) {
        const uint32_t d0 = sb + (c % 3) * STAGE
                          + (arow + 64 * hf) * ROWB + acol * 8;
        #pragma unroll
        for (int p = 0; p < 4; ++p) {
            __half2 h0 = __floats2half2_rn(v[p].x, v[p].y);
            __half2 h1 = __floats2half2_rn(v[p].z, v[p].w);
            uint32_t u0, u1;
            memcpy(&u0, &h0, 4); memcpy(&u1, &h1, 4);
            STS64(d0 + p * 16 * ROWB, u0, u1);
        }
    };

    float sc00 = 0.f, sc01 = 0.f, sc10 = 0.f, sc11 = 0.f;
    float acc[2][8][4];
    #pragma unroll
    for (int mi = 0; mi < 2; ++mi)
        #pragma unroll
        for (int ni = 0; ni < 8; ++ni)
            #pragma unroll
            for (int cc = 0; cc < 4; ++cc) acc[mi][ni][cc] = 0.f;

    // ---------- prologue ----------
    issue_b(0);
    issue_b(1);
    {   // A chunk 0 direct (stage 0)
        float4 v[4];
        ldg_a(0, 0, v); sts_a(0, 0, v);
        ldg_a(0, 1, v); sts_a(0, 1, v);
    }
    if (tid < NT) {
        q_s[tid]  = g_q[b * HH + tid];
        wv_s[tid] = wv[tid];
    }

    #pragma unroll 1
    for (int c = 0; c < TOTC; ++c) {
        if (c + 1 < TOTC) { CPASYNC_WAIT1(); } else { CPASYNC_WAIT0(); }
        __syncthreads();   // chunk c (A sts'd at c-1, B cp.async) visible;
                           // orders iter c-2 reads of stage (c+1)%3 and
                           // iter c-1 reads of stage (c+2)%3 before writes

        if (c + 2 < TOTC) issue_b(c + 2);

        // stage q/wv for the NEXT pass at each pass start
        if ((c & (NC - 1)) == 0 && (c >> 4) + 1 < NPASS && tid < NT) {
            const int npn = (c >> 4) + 1;
            q_s[(npn & 1) * 128 + tid]  = g_q[b * HH + npn * NT + tid];
            wv_s[(npn & 1) * 128 + tid] = wv[npn * NT + tid];
        }

        const uint32_t Abase = sb + (c % 3) * STAGE;
        const uint32_t Bbase = Abase + ATILE;
        const bool more = (c + 1 < TOTC);
        float4 av[4];
        if (more) ldg_a(c + 1, 0, av);   // prefetch next-A half 0 (fp32)

        // ---------- MMA over chunk c, interleaved with A convert ----------
        #pragma unroll
        for (int half = 0; half < 2; ++half) {
            #pragma unroll
            for (int kss = 0; kss < 2; ++kss) {
                const int ks = half * 2 + kss;
                const uint32_t koff = ks * 32;       // 16 fp16 = 32 B
                uint32_t ah[2][4];
                #pragma unroll
                for (int mi = 0; mi < 2; ++mi)
                    LDSM4(ah[mi], Abase + (wm * 32 + mi * 16) * ROWB + a_lane + koff);
                uint32_t bh[2][4];
                LDSM4(bh[0], Bbase + (wn * 64) * ROWB + b_lane + koff);
                #pragma unroll
                for (int nq = 0; nq < 4; ++nq) {     // 16 n per ldsm.x4
                    if (nq < 3)  // prefetch next B-frag group
                        LDSM4(bh[(nq + 1) & 1],
                              Bbase + (wn * 64 + (nq + 1) * 16) * ROWB + b_lane + koff);
                    const uint32_t* bq = bh[nq & 1];
                    #pragma unroll
                    for (int h2 = 0; h2 < 2; ++h2)
                        #pragma unroll
                        for (int mi = 0; mi < 2; ++mi)
                            MMA16816(acc[mi][nq * 2 + h2], ah[mi],
                                     bq[h2 * 2], bq[h2 * 2 + 1]);
                }
            }
            if (more) {
                sts_a(c + 1, half, av);              // store converted half
                if (half == 0) ldg_a(c + 1, 1, av);  // prefetch half 1
            }
        }

        // ---------- pass epilogue: tanh + dot with w_v ----------
        if ((c & (NC - 1)) == NC - 1) {
            const int par = (c >> 4) & 1;
            const float* qp = q_s + par * 128;
            const float* wp = wv_s + par * 128;
            #pragma unroll
            for (int mi = 0; mi < 2; ++mi) {
                #pragma unroll
                for (int ni = 0; ni < 8; ++ni) {
                    const int col0 = wn * 64 + ni * 8 + (lane & 3) * 2;
                    const float q0 = qp[col0],  q1 = qp[col0 + 1];
                    const float w0 = wp[col0],  w1 = wp[col0 + 1];
                    float* cp = acc[mi][ni];
                    const float p0 = tanhf(cp[0] + q0) * w0 + tanhf(cp[1] + q1) * w1;
                    const float p1 = tanhf(cp[2] + q0) * w0 + tanhf(cp[3] + q1) * w1;
                    if (mi == 0) { sc00 += p0; sc01 += p1; }
                    else         { sc10 += p0; sc11 += p1; }
                    cp[0] = cp[1] = cp[2] = cp[3] = 0.f;
                }
            }
        }
    }

    // ---------- final reduction ----------
    sc00 += __shfl_xor_sync(~0u, sc00, 1); sc00 += __shfl_xor_sync(~0u, sc00, 2);
    sc01 += __shfl_xor_sync(~0u, sc01, 1); sc01 += __shfl_xor_sync(~0u, sc01, 2);
    sc10 += __shfl_xor_sync(~0u, sc10, 1); sc10 += __shfl_xor_sync(~0u, sc10, 2);
    sc11 += __shfl_xor_sync(~0u, sc11, 1); sc11 += __shfl_xor_sync(~0u, sc11, 2);
    if ((lane & 3) == 0) {
        const int g = lane >> 2;
        red[wn * 128 + wm * 32 + g]      = sc00;
        red[wn * 128 + wm * 32 + 8 + g]  = sc01;
        red[wn * 128 + wm * 32 + 16 + g] = sc10;
        red[wn * 128 + wm * 32 + 24 + g] = sc11;
    }
    __syncthreads();
    if (tid < MT) out[m0 + tid] = red[tid] + red[128 + tid];
}

// ================= launch =================
extern "C" void kernel_launch(void* const* d_in, const int* in_sizes, int n_in,
                              void* d_out, int out_size) {
    const float* queries = (const float*)d_in[0];  // [16,1,1024]
    const float* keys    = (const float*)d_in[1];  // [16,8192,1024]
    const float* Wq      = (const float*)d_in[2];  // [1024,1024]
    const float* Wk      = (const float*)d_in[3];  // [1024,1024]
    const float* wv      = (const float*)d_in[4];  // [1024,1]
    float* out = (float*)d_out;                    // [16,8192]

    cudaFuncSetAttribute(additive_attn_main,
                         cudaFuncAttributeMaxDynamicSharedMemorySize, SMEM_TOTAL);

    wsplit_kernel<<<dim3(HH / 32, DD / 32), dim3(32, 8)>>>(Wk);
    qproj_kernel<<<dim3(HH / 256, BB), 256>>>(queries, Wq);
    additive_attn_main<<<MTOT / MT, THREADS, SMEM_TOTAL>>>(keys, wv, out);
}